// round 5
// baseline (speedup 1.0000x reference)
#include <cuda_runtime.h>
#include <math.h>
#include <stdint.h>

#define N_CTX   4096
#define D_MODEL 2048

// ---------------------------------------------------------------------------
// Scratch (__device__ globals; allocation-free rule)
// ---------------------------------------------------------------------------
__device__ float g_xb  [(size_t)N_CTX * D_MODEL];
__device__ float g_xs  [(size_t)N_CTX * D_MODEL];
__device__ float g_xTb [(size_t)D_MODEL * N_CTX];   // x^T, tf32-rounded
__device__ float g_wqkb[(size_t)D_MODEL * D_MODEL];
__device__ float g_wqks[(size_t)D_MODEL * D_MODEL];
__device__ float g_wovb[(size_t)D_MODEL * D_MODEL];
__device__ float g_Qb  [(size_t)N_CTX * D_MODEL];
__device__ float g_Qs  [(size_t)N_CTX * D_MODEL];
__device__ float g_S   [(size_t)N_CTX * N_CTX];
__device__ float g_A   [(size_t)N_CTX * D_MODEL];

// ---------------------------------------------------------------------------
// helpers
// ---------------------------------------------------------------------------
__device__ __forceinline__ float f2tf32f(float x) {
    uint32_t r;
    asm("cvt.rna.tf32.f32 %0, %1;" : "=r"(r) : "f"(x));
    return __uint_as_float(r);
}

__device__ __forceinline__ void mma_tf32(float c[4],
                                         float a0, float a1, float a2, float a3,
                                         float b0, float b1) {
    asm volatile(
        "mma.sync.aligned.m16n8k8.row.col.f32.tf32.tf32.f32 "
        "{%0,%1,%2,%3}, {%4,%5,%6,%7}, {%8,%9}, {%0,%1,%2,%3};"
        : "+f"(c[0]), "+f"(c[1]), "+f"(c[2]), "+f"(c[3])
        : "r"(__float_as_uint(a0)), "r"(__float_as_uint(a1)),
          "r"(__float_as_uint(a2)), "r"(__float_as_uint(a3)),
          "r"(__float_as_uint(b0)), "r"(__float_as_uint(b1)));
}

__device__ __forceinline__ void cp_async16(void* smem, const void* gmem) {
    uint32_t s = (uint32_t)__cvta_generic_to_shared(smem);
    asm volatile("cp.async.cg.shared.global [%0], [%1], 16;" :: "r"(s), "l"(gmem));
}

// ---------------------------------------------------------------------------
// Elementwise pre-passes
// ---------------------------------------------------------------------------
__global__ __launch_bounds__(256)
void split_tf32_kernel(const float* __restrict__ src,
                       float* __restrict__ big, float* __restrict__ sml, int n4)
{
    int i = blockIdx.x * 256 + threadIdx.x;
    if (i >= n4) return;
    float4 v = ((const float4*)src)[i];
    float4 b, s;
    b.x = f2tf32f(v.x); s.x = f2tf32f(v.x - b.x);
    b.y = f2tf32f(v.y); s.y = f2tf32f(v.y - b.y);
    b.z = f2tf32f(v.z); s.z = f2tf32f(v.z - b.z);
    b.w = f2tf32f(v.w); s.w = f2tf32f(v.w - b.w);
    ((float4*)big)[i] = b;
    ((float4*)sml)[i] = s;
}

__global__ __launch_bounds__(256)
void round_tf32_kernel(const float* __restrict__ src, float* __restrict__ dst, int n4)
{
    int i = blockIdx.x * 256 + threadIdx.x;
    if (i >= n4) return;
    float4 v = ((const float4*)src)[i];
    v.x = f2tf32f(v.x); v.y = f2tf32f(v.y); v.z = f2tf32f(v.z); v.w = f2tf32f(v.w);
    ((float4*)dst)[i] = v;
}

// dst[Ccols, R] = tf32(src[R, Ccols]^T)
__global__ __launch_bounds__(256)
void transpose_tf32_kernel(const float* __restrict__ src, float* __restrict__ dst,
                           int R, int Ccols)
{
    __shared__ float t[32][33];
    int bx = blockIdx.x * 32, by = blockIdx.y * 32;
    int x = bx + threadIdx.x;
    for (int i = threadIdx.y; i < 32; i += 8)
        t[i][threadIdx.x] = src[(size_t)(by + i) * Ccols + x];
    __syncthreads();
    int ox = by + threadIdx.x;
    for (int i = threadIdx.y; i < 32; i += 8)
        dst[(size_t)(bx + i) * R + ox] = f2tf32f(t[threadIdx.x][i]);
}

// ---------------------------------------------------------------------------
// tf32 mma.sync GEMM: C[M,N] = A[M,K] @ B^T, A:[M,K], B:[N,K] (both K-major).
//   CSKIP: skip blocks fully above diagonal; CK: k-range limited to m0+128
//   SPLIT: 3xTF32 compensated (pass order AmBb, AbBm, AbBb — no RAW chains)
//   EPI:   0 plain | 1 split store (C=big, C2=small) | 2 tf32-rounded store
// 512 threads (16 warps = 4/SMSP), warp tile 32x32, block 128x128x16.
// All operands are pre-rounded tf32 values in fp32 storage (no cvt in loop).
// ---------------------------------------------------------------------------
template <int CSKIP, int CK, int SPLIT, int EPI>
__global__ __launch_bounds__(512, 1)
void mma_gemm(const float* __restrict__ Ab_, const float* __restrict__ As_,
              const float* __restrict__ Bb_, const float* __restrict__ Bs_,
              float* __restrict__ C, float* __restrict__ C2,
              int M, int N, int K)
{
    constexpr int BM = 128, BN = 128, BK = 16, LDP = 20;
    constexpr int BMs = SPLIT ? BM : 1;
    constexpr int BNs = SPLIT ? BN : 1;

    __shared__ float sAb[2][BM][LDP];
    __shared__ float sBb[2][BN][LDP];
    __shared__ float sAs[2][BMs][LDP];
    __shared__ float sBs[2][BNs][LDP];

    const int m0 = blockIdx.y * BM;
    const int n0 = blockIdx.x * BN;
    if (CSKIP && n0 >= m0 + BM) return;

    const int kEnd = CK ? min(K, m0 + BM) : K;
    const int nK   = kEnd / BK;

    const int tid  = threadIdx.x;
    const int warp = tid >> 5;
    const int lane = tid & 31;
    const int wm0  = (warp & 3) * 32;    // 4x4 warp grid
    const int wn0  = (warp >> 2) * 32;
    const int g    = lane >> 2;
    const int tg   = lane & 3;

    float acc[2][4][4];
    #pragma unroll
    for (int i = 0; i < 2; i++)
        #pragma unroll
        for (int j = 0; j < 4; j++)
            #pragma unroll
            for (int r = 0; r < 4; r++) acc[i][j][r] = 0.0f;

    // 512 threads load 512 float4-chunks per 128x16 tile: 1 chunk each.
    const int lrow = tid >> 2;           // 0..127
    const int lc4  = (tid & 3) * 4;      // 0,4,8,12

    auto loadStage = [&](int buf, int k0) {
        cp_async16(&sAb[buf][lrow][lc4], Ab_ + (size_t)(m0 + lrow) * K + k0 + lc4);
        cp_async16(&sBb[buf][lrow][lc4], Bb_ + (size_t)(n0 + lrow) * K + k0 + lc4);
        if constexpr (SPLIT) {
            cp_async16(&sAs[buf][lrow][lc4], As_ + (size_t)(m0 + lrow) * K + k0 + lc4);
            cp_async16(&sBs[buf][lrow][lc4], Bs_ + (size_t)(n0 + lrow) * K + k0 + lc4);
        }
    };

    auto compute = [&](int buf) {
        #pragma unroll
        for (int ks = 0; ks < 2; ks++) {
            const int kb = ks * 8;
            float Ab[2][4], Am[2][4];
            float Bb[4][2], Bm[4][2];

            #pragma unroll
            for (int mt = 0; mt < 2; mt++) {
                Ab[mt][0] = sAb[buf][wm0 + mt * 16 + g    ][kb + tg    ];
                Ab[mt][1] = sAb[buf][wm0 + mt * 16 + g + 8][kb + tg    ];
                Ab[mt][2] = sAb[buf][wm0 + mt * 16 + g    ][kb + tg + 4];
                Ab[mt][3] = sAb[buf][wm0 + mt * 16 + g + 8][kb + tg + 4];
                if constexpr (SPLIT) {
                    Am[mt][0] = sAs[buf][wm0 + mt * 16 + g    ][kb + tg    ];
                    Am[mt][1] = sAs[buf][wm0 + mt * 16 + g + 8][kb + tg    ];
                    Am[mt][2] = sAs[buf][wm0 + mt * 16 + g    ][kb + tg + 4];
                    Am[mt][3] = sAs[buf][wm0 + mt * 16 + g + 8][kb + tg + 4];
                }
            }
            #pragma unroll
            for (int nt = 0; nt < 4; nt++) {
                Bb[nt][0] = sBb[buf][wn0 + nt * 8 + g][kb + tg    ];
                Bb[nt][1] = sBb[buf][wn0 + nt * 8 + g][kb + tg + 4];
                if constexpr (SPLIT) {
                    Bm[nt][0] = sBs[buf][wn0 + nt * 8 + g][kb + tg    ];
                    Bm[nt][1] = sBs[buf][wn0 + nt * 8 + g][kb + tg + 4];
                }
            }
            // Pass-ordered: consecutive MMAs hit different accumulators.
            if constexpr (SPLIT) {
                #pragma unroll
                for (int mt = 0; mt < 2; mt++)
                    #pragma unroll
                    for (int nt = 0; nt < 4; nt++)
                        mma_tf32(acc[mt][nt], Am[mt][0], Am[mt][1], Am[mt][2], Am[mt][3],
                                 Bb[nt][0], Bb[nt][1]);
                #pragma unroll
                for (int mt = 0; mt < 2; mt++)
                    #pragma unroll
                    for (int nt = 0; nt < 4; nt++)
                        mma_tf32(acc[mt][nt], Ab[mt][0], Ab[mt][1], Ab[mt][2], Ab[mt][3],
                                 Bm[nt][0], Bm[nt][1]);
            }
            #pragma unroll
            for (int mt = 0; mt < 2; mt++)
                #pragma unroll
                for (int nt = 0; nt < 4; nt++)
                    mma_tf32(acc[mt][nt], Ab[mt][0], Ab[mt][1], Ab[mt][2], Ab[mt][3],
                             Bb[nt][0], Bb[nt][1]);
        }
    };

    loadStage(0, 0);
    asm volatile("cp.async.commit_group;" ::: "memory");

    for (int kt = 0; kt < nK; kt++) {
        if (kt + 1 < nK) {
            loadStage((kt + 1) & 1, (kt + 1) * BK);
            asm volatile("cp.async.commit_group;" ::: "memory");
            asm volatile("cp.async.wait_group 1;" ::: "memory");
        } else {
            asm volatile("cp.async.wait_group 0;" ::: "memory");
        }
        __syncthreads();
        compute(kt & 1);
        __syncthreads();
    }

    // ---- epilogue ----
    #pragma unroll
    for (int mt = 0; mt < 2; mt++) {
        #pragma unroll
        for (int nt = 0; nt < 4; nt++) {
            int r = m0 + wm0 + mt * 16 + g;
            int c = n0 + wn0 + nt * 8 + 2 * tg;
            #pragma unroll
            for (int h = 0; h < 2; h++) {
                float v0 = acc[mt][nt][h * 2 + 0];
                float v1 = acc[mt][nt][h * 2 + 1];
                size_t off = (size_t)(r + h * 8) * N + c;
                if constexpr (EPI == 0) {
                    *(float2*)(C + off) = make_float2(v0, v1);
                } else if constexpr (EPI == 1) {
                    float b0 = f2tf32f(v0), b1 = f2tf32f(v1);
                    *(float2*)(C  + off) = make_float2(b0, b1);
                    *(float2*)(C2 + off) = make_float2(f2tf32f(v0 - b0), f2tf32f(v1 - b1));
                } else {
                    *(float2*)(C + off) = make_float2(f2tf32f(v0), f2tf32f(v1));
                }
            }
        }
    }
}

// ---------------------------------------------------------------------------
// Causal row softmax, in place; output tf32-rounded (incl. zero tail).
// ---------------------------------------------------------------------------
__global__ __launch_bounds__(256)
void softmax_kernel(float* __restrict__ S, int n)
{
    const int row   = blockIdx.x;
    float* srow     = S + (size_t)row * n;
    const int valid = row + 1;
    const int tid   = threadIdx.x;

    __shared__ float red[256];

    float m = -INFINITY;
    for (int j = tid; j < valid; j += 256) m = fmaxf(m, srow[j]);
    red[tid] = m;
    __syncthreads();
    #pragma unroll
    for (int s = 128; s > 0; s >>= 1) {
        if (tid < s) red[tid] = fmaxf(red[tid], red[tid + s]);
        __syncthreads();
    }
    m = red[0];
    __syncthreads();

    float sum = 0.0f;
    for (int j = tid; j < valid; j += 256) {
        float e = __expf(srow[j] - m);
        srow[j] = e;
        sum += e;
    }
    red[tid] = sum;
    __syncthreads();
    #pragma unroll
    for (int s = 128; s > 0; s >>= 1) {
        if (tid < s) red[tid] += red[tid + s];
        __syncthreads();
    }
    const float inv = 1.0f / red[0];

    for (int j = tid; j < n; j += 256)
        srow[j] = (j < valid) ? f2tf32f(srow[j] * inv) : 0.0f;
}

// ---------------------------------------------------------------------------
extern "C" void kernel_launch(void* const* d_in, const int* in_sizes, int n_in,
                              void* d_out, int out_size)
{
    const float* x   = (const float*)d_in[0];
    const float* Wqk = (const float*)d_in[1];
    const float* Wov = (const float*)d_in[2];
    float* out       = (float*)d_out;

    float *xb, *xs, *xTb, *wqkb, *wqks, *wovb, *Qb, *Qs, *S, *A;
    cudaGetSymbolAddress((void**)&xb,   g_xb);
    cudaGetSymbolAddress((void**)&xs,   g_xs);
    cudaGetSymbolAddress((void**)&xTb,  g_xTb);
    cudaGetSymbolAddress((void**)&wqkb, g_wqkb);
    cudaGetSymbolAddress((void**)&wqks, g_wqks);
    cudaGetSymbolAddress((void**)&wovb, g_wovb);
    cudaGetSymbolAddress((void**)&Qb,   g_Qb);
    cudaGetSymbolAddress((void**)&Qs,   g_Qs);
    cudaGetSymbolAddress((void**)&S,    g_S);
    cudaGetSymbolAddress((void**)&A,    g_A);

    const int nx4 = N_CTX * D_MODEL / 4;
    const int nw4 = D_MODEL * D_MODEL / 4;

    // Pre-passes: split x and Wqk, round Wov, build tf32 x^T
    split_tf32_kernel<<<(nx4 + 255) / 256, 256>>>(x, xb, xs, nx4);
    split_tf32_kernel<<<(nw4 + 255) / 256, 256>>>(Wqk, wqkb, wqks, nw4);
    round_tf32_kernel<<<(nw4 + 255) / 256, 256>>>(Wov, wovb, nw4);
    transpose_tf32_kernel<<<dim3(D_MODEL / 32, N_CTX / 32), dim3(32, 8)>>>(x, xTb, N_CTX, D_MODEL);

    // 1) Q = x @ Wqk^T  (3xTF32; epilogue writes split Qb/Qs)
    mma_gemm<0, 0, 1, 1><<<dim3(D_MODEL / 128, N_CTX / 128), 512>>>(
        xb, xs, wqkb, wqks, Qb, Qs, N_CTX, D_MODEL, D_MODEL);

    // 2) S = Q @ x^T  (causal blocks only, 3xTF32)
    mma_gemm<1, 0, 1, 0><<<dim3(N_CTX / 128, N_CTX / 128), 512>>>(
        Qb, Qs, xb, xs, S, nullptr, N_CTX, N_CTX, D_MODEL);

    // 3) P = causal_softmax(S), in place, tf32-rounded
    softmax_kernel<<<N_CTX, 256>>>(S, N_CTX);

    // 4) A = P @ (x^T)^T  (plain tf32, causal k-limit; A rounded tf32)
    mma_gemm<0, 1, 0, 2><<<dim3(D_MODEL / 128, N_CTX / 128), 512>>>(
        S, nullptr, xTb, nullptr, A, nullptr, N_CTX, D_MODEL, N_CTX);

    // 5) out = A @ Wov^T  (plain tf32)
    mma_gemm<0, 0, 0, 0><<<dim3(D_MODEL / 128, N_CTX / 128), 512>>>(
        A, nullptr, wovb, nullptr, out, nullptr, N_CTX, D_MODEL, D_MODEL);
}

// round 6
// speedup vs baseline: 1.7565x; 1.7565x over previous
#include <cuda_runtime.h>
#include <cuda_fp16.h>
#include <math.h>
#include <stdint.h>

#define N_CTX   4096
#define D_MODEL 2048

// ---------------------------------------------------------------------------
// Scratch (__device__ globals; allocation-free rule)
// ---------------------------------------------------------------------------
__device__ __half g_xb16 [(size_t)N_CTX * D_MODEL];
__device__ __half g_xs16 [(size_t)N_CTX * D_MODEL];
__device__ __half g_xT16 [(size_t)D_MODEL * N_CTX];   // x^T, single fp16
__device__ __half g_wqkb16[(size_t)D_MODEL * D_MODEL];
__device__ __half g_wqks16[(size_t)D_MODEL * D_MODEL];
__device__ __half g_wov16 [(size_t)D_MODEL * D_MODEL];
__device__ __half g_Qb16 [(size_t)N_CTX * D_MODEL];
__device__ __half g_Qs16 [(size_t)N_CTX * D_MODEL];
__device__ float  g_S    [(size_t)N_CTX * N_CTX];
__device__ __half g_Pb16 [(size_t)N_CTX * N_CTX];
__device__ __half g_Ps16 [(size_t)N_CTX * N_CTX];
__device__ __half g_Ab16 [(size_t)N_CTX * D_MODEL];
__device__ __half g_As16 [(size_t)N_CTX * D_MODEL];

// ---------------------------------------------------------------------------
// helpers
// ---------------------------------------------------------------------------
__device__ __forceinline__ void mma_f16(float c[4],
                                        uint32_t a0, uint32_t a1, uint32_t a2, uint32_t a3,
                                        uint32_t b0, uint32_t b1) {
    asm volatile(
        "mma.sync.aligned.m16n8k16.row.col.f32.f16.f16.f32 "
        "{%0,%1,%2,%3}, {%4,%5,%6,%7}, {%8,%9}, {%0,%1,%2,%3};"
        : "+f"(c[0]), "+f"(c[1]), "+f"(c[2]), "+f"(c[3])
        : "r"(a0), "r"(a1), "r"(a2), "r"(a3), "r"(b0), "r"(b1));
}

__device__ __forceinline__ void cp_async16(void* smem, const void* gmem) {
    uint32_t s = (uint32_t)__cvta_generic_to_shared(smem);
    asm volatile("cp.async.cg.shared.global [%0], [%1], 16;" :: "r"(s), "l"(gmem));
}

// ---------------------------------------------------------------------------
// Elementwise pre-passes
// ---------------------------------------------------------------------------
// Split fp32 -> (big fp16, small fp16) pair: v ~= hb + hs to ~22 bits.
__global__ __launch_bounds__(256)
void split_f16_kernel(const float* __restrict__ src,
                      __half* __restrict__ big, __half* __restrict__ sml, int n4)
{
    int i = blockIdx.x * 256 + threadIdx.x;
    if (i >= n4) return;
    float4 v = ((const float4*)src)[i];
    __half b0 = __float2half_rn(v.x), b1 = __float2half_rn(v.y);
    __half b2 = __float2half_rn(v.z), b3 = __float2half_rn(v.w);
    __half s0 = __float2half_rn(v.x - __half2float(b0));
    __half s1 = __float2half_rn(v.y - __half2float(b1));
    __half s2 = __float2half_rn(v.z - __half2float(b2));
    __half s3 = __float2half_rn(v.w - __half2float(b3));
    ((__half2*)big)[i * 2 + 0] = __halves2half2(b0, b1);
    ((__half2*)big)[i * 2 + 1] = __halves2half2(b2, b3);
    ((__half2*)sml)[i * 2 + 0] = __halves2half2(s0, s1);
    ((__half2*)sml)[i * 2 + 1] = __halves2half2(s2, s3);
}

__global__ __launch_bounds__(256)
void round_f16_kernel(const float* __restrict__ src, __half* __restrict__ dst, int n4)
{
    int i = blockIdx.x * 256 + threadIdx.x;
    if (i >= n4) return;
    float4 v = ((const float4*)src)[i];
    ((__half2*)dst)[i * 2 + 0] = __halves2half2(__float2half_rn(v.x), __float2half_rn(v.y));
    ((__half2*)dst)[i * 2 + 1] = __halves2half2(__float2half_rn(v.z), __float2half_rn(v.w));
}

// dst[Ccols, R] = fp16(src[R, Ccols]^T)
__global__ __launch_bounds__(256)
void transpose_f16_kernel(const float* __restrict__ src, __half* __restrict__ dst,
                          int R, int Ccols)
{
    __shared__ float t[32][33];
    int bx = blockIdx.x * 32, by = blockIdx.y * 32;
    int x = bx + threadIdx.x;
    for (int i = threadIdx.y; i < 32; i += 8)
        t[i][threadIdx.x] = src[(size_t)(by + i) * Ccols + x];
    __syncthreads();
    int ox = by + threadIdx.x;
    for (int i = threadIdx.y; i < 32; i += 8)
        dst[(size_t)(bx + i) * R + ox] = __float2half_rn(t[threadIdx.x][i]);
}

// ---------------------------------------------------------------------------
// fp16 split GEMM: C[M,N] = A[M,K] @ B^T, A:[M,K], B:[N,K], both K-major fp16.
//   PASSES=3: (As*Bb + Ab*Bs + Ab*Bb)  — ~22-bit effective operands
//   PASSES=2: (As*Bb + Ab*Bb)          — A split, B single-rounded
//   CSKIP: skip blocks above diagonal; CK: k-range limited to m0+128
//   EPI: 0 = fp32 store to C; 1 = split fp16 store to Cb/Cs
// 256 threads, 8 warps (2x4), warp tile 64x32, block 128x128x32, m16n8k16.
// ---------------------------------------------------------------------------
template <int CSKIP, int CK, int PASSES, int EPI>
__global__ __launch_bounds__(256)
void hgemm(const __half* __restrict__ Ab_, const __half* __restrict__ As_,
           const __half* __restrict__ Bb_, const __half* __restrict__ Bs_,
           float* __restrict__ C, __half* __restrict__ Cb, __half* __restrict__ Cs,
           int M, int N, int K)
{
    constexpr int BM = 128, BN = 128, BK = 32, PK = 40;  // PK: padded halves/row
    constexpr int BNs = (PASSES == 3) ? BN : 1;

    __shared__ __half sAb[2][BM][PK];
    __shared__ __half sAs[2][BM][PK];
    __shared__ __half sBb[2][BN][PK];
    __shared__ __half sBs[2][BNs][PK];

    const int m0 = blockIdx.y * BM;
    const int n0 = blockIdx.x * BN;
    if (CSKIP && n0 >= m0 + BM) return;

    const int kEnd = CK ? min(K, m0 + BM) : K;
    const int nK   = kEnd / BK;

    const int tid  = threadIdx.x;
    const int warp = tid >> 5;
    const int lane = tid & 31;
    const int wm0  = (warp & 1) * 64;
    const int wn0  = (warp >> 1) * 32;
    const int g    = lane >> 2;
    const int tg   = lane & 3;

    float acc[4][4][4];
    #pragma unroll
    for (int i = 0; i < 4; i++)
        #pragma unroll
        for (int j = 0; j < 4; j++)
            #pragma unroll
            for (int r = 0; r < 4; r++) acc[i][j][r] = 0.0f;

    auto loadStage = [&](int buf, int k0) {
        #pragma unroll
        for (int i = 0; i < 2; i++) {
            int idx = tid + i * 256;          // 0..511
            int row = idx >> 2;               // 0..127
            int c8  = (idx & 3) * 8;          // halves offset: 0,8,16,24
            cp_async16(&sAb[buf][row][c8], Ab_ + (size_t)(m0 + row) * K + k0 + c8);
            cp_async16(&sAs[buf][row][c8], As_ + (size_t)(m0 + row) * K + k0 + c8);
            cp_async16(&sBb[buf][row][c8], Bb_ + (size_t)(n0 + row) * K + k0 + c8);
            if constexpr (PASSES == 3)
                cp_async16(&sBs[buf][row][c8], Bs_ + (size_t)(n0 + row) * K + k0 + c8);
        }
    };

    auto compute = [&](int buf) {
        #pragma unroll
        for (int ks = 0; ks < 2; ks++) {
            const int kb = ks * 16;
            uint32_t Ab[4][4], As[4][4];
            uint32_t Bb[4][2], Bs[4][2];

            #pragma unroll
            for (int mt = 0; mt < 4; mt++) {
                const int rb = wm0 + mt * 16;
                Ab[mt][0] = *(const uint32_t*)&sAb[buf][rb + g    ][kb + 2 * tg    ];
                Ab[mt][1] = *(const uint32_t*)&sAb[buf][rb + g + 8][kb + 2 * tg    ];
                Ab[mt][2] = *(const uint32_t*)&sAb[buf][rb + g    ][kb + 2 * tg + 8];
                Ab[mt][3] = *(const uint32_t*)&sAb[buf][rb + g + 8][kb + 2 * tg + 8];
                As[mt][0] = *(const uint32_t*)&sAs[buf][rb + g    ][kb + 2 * tg    ];
                As[mt][1] = *(const uint32_t*)&sAs[buf][rb + g + 8][kb + 2 * tg    ];
                As[mt][2] = *(const uint32_t*)&sAs[buf][rb + g    ][kb + 2 * tg + 8];
                As[mt][3] = *(const uint32_t*)&sAs[buf][rb + g + 8][kb + 2 * tg + 8];
            }
            #pragma unroll
            for (int nt = 0; nt < 4; nt++) {
                const int rb = wn0 + nt * 8 + g;
                Bb[nt][0] = *(const uint32_t*)&sBb[buf][rb][kb + 2 * tg    ];
                Bb[nt][1] = *(const uint32_t*)&sBb[buf][rb][kb + 2 * tg + 8];
                if constexpr (PASSES == 3) {
                    Bs[nt][0] = *(const uint32_t*)&sBs[buf][rb][kb + 2 * tg    ];
                    Bs[nt][1] = *(const uint32_t*)&sBs[buf][rb][kb + 2 * tg + 8];
                }
            }
            // Pass-ordered: consecutive MMAs hit different accumulators.
            #pragma unroll
            for (int mt = 0; mt < 4; mt++)
                #pragma unroll
                for (int nt = 0; nt < 4; nt++)
                    mma_f16(acc[mt][nt], As[mt][0], As[mt][1], As[mt][2], As[mt][3],
                            Bb[nt][0], Bb[nt][1]);
            if constexpr (PASSES == 3) {
                #pragma unroll
                for (int mt = 0; mt < 4; mt++)
                    #pragma unroll
                    for (int nt = 0; nt < 4; nt++)
                        mma_f16(acc[mt][nt], Ab[mt][0], Ab[mt][1], Ab[mt][2], Ab[mt][3],
                                Bs[nt][0], Bs[nt][1]);
            }
            #pragma unroll
            for (int mt = 0; mt < 4; mt++)
                #pragma unroll
                for (int nt = 0; nt < 4; nt++)
                    mma_f16(acc[mt][nt], Ab[mt][0], Ab[mt][1], Ab[mt][2], Ab[mt][3],
                            Bb[nt][0], Bb[nt][1]);
        }
    };

    loadStage(0, 0);
    asm volatile("cp.async.commit_group;" ::: "memory");

    for (int kt = 0; kt < nK; kt++) {
        if (kt + 1 < nK) {
            loadStage((kt + 1) & 1, (kt + 1) * BK);
            asm volatile("cp.async.commit_group;" ::: "memory");
            asm volatile("cp.async.wait_group 1;" ::: "memory");
        } else {
            asm volatile("cp.async.wait_group 0;" ::: "memory");
        }
        __syncthreads();
        compute(kt & 1);
        __syncthreads();
    }

    // ---- epilogue ----
    #pragma unroll
    for (int mt = 0; mt < 4; mt++) {
        #pragma unroll
        for (int nt = 0; nt < 4; nt++) {
            int r = m0 + wm0 + mt * 16 + g;
            int c = n0 + wn0 + nt * 8 + 2 * tg;
            #pragma unroll
            for (int h = 0; h < 2; h++) {
                float v0 = acc[mt][nt][h * 2 + 0];
                float v1 = acc[mt][nt][h * 2 + 1];
                size_t off = (size_t)(r + h * 8) * N + c;
                if constexpr (EPI == 0) {
                    *(float2*)(C + off) = make_float2(v0, v1);
                } else {
                    __half b0 = __float2half_rn(v0), b1 = __float2half_rn(v1);
                    *(__half2*)(Cb + off) = __halves2half2(b0, b1);
                    *(__half2*)(Cs + off) = __halves2half2(
                        __float2half_rn(v0 - __half2float(b0)),
                        __float2half_rn(v1 - __half2float(b1)));
                }
            }
        }
    }
}

// ---------------------------------------------------------------------------
// Causal row softmax: reads fp32 scores, writes split-fp16 P (zero tail).
// ---------------------------------------------------------------------------
__global__ __launch_bounds__(256)
void softmax_kernel(float* __restrict__ S,
                    __half* __restrict__ Pb, __half* __restrict__ Ps, int n)
{
    const int row   = blockIdx.x;
    float* srow     = S + (size_t)row * n;
    const int valid = row + 1;
    const int tid   = threadIdx.x;

    __shared__ float red[256];

    float m = -INFINITY;
    for (int j = tid; j < valid; j += 256) m = fmaxf(m, srow[j]);
    red[tid] = m;
    __syncthreads();
    #pragma unroll
    for (int s = 128; s > 0; s >>= 1) {
        if (tid < s) red[tid] = fmaxf(red[tid], red[tid + s]);
        __syncthreads();
    }
    m = red[0];
    __syncthreads();

    float sum = 0.0f;
    for (int j = tid; j < valid; j += 256) {
        float e = __expf(srow[j] - m);
        srow[j] = e;
        sum += e;
    }
    red[tid] = sum;
    __syncthreads();
    #pragma unroll
    for (int s = 128; s > 0; s >>= 1) {
        if (tid < s) red[tid] += red[tid + s];
        __syncthreads();
    }
    const float inv = 1.0f / red[0];

    for (int j = tid; j < n; j += 256) {
        float p = (j < valid) ? srow[j] * inv : 0.0f;
        __half b = __float2half_rn(p);
        Pb[(size_t)row * n + j] = b;
        Ps[(size_t)row * n + j] = __float2half_rn(p - __half2float(b));
    }
}

// ---------------------------------------------------------------------------
extern "C" void kernel_launch(void* const* d_in, const int* in_sizes, int n_in,
                              void* d_out, int out_size)
{
    const float* x   = (const float*)d_in[0];
    const float* Wqk = (const float*)d_in[1];
    const float* Wov = (const float*)d_in[2];
    float* out       = (float*)d_out;

    __half *xb, *xs, *xT, *wqkb, *wqks, *wov, *Qb, *Qs, *Pb, *Ps, *Ab, *As;
    float *S;
    cudaGetSymbolAddress((void**)&xb,   g_xb16);
    cudaGetSymbolAddress((void**)&xs,   g_xs16);
    cudaGetSymbolAddress((void**)&xT,   g_xT16);
    cudaGetSymbolAddress((void**)&wqkb, g_wqkb16);
    cudaGetSymbolAddress((void**)&wqks, g_wqks16);
    cudaGetSymbolAddress((void**)&wov,  g_wov16);
    cudaGetSymbolAddress((void**)&Qb,   g_Qb16);
    cudaGetSymbolAddress((void**)&Qs,   g_Qs16);
    cudaGetSymbolAddress((void**)&S,    g_S);
    cudaGetSymbolAddress((void**)&Pb,   g_Pb16);
    cudaGetSymbolAddress((void**)&Ps,   g_Ps16);
    cudaGetSymbolAddress((void**)&Ab,   g_Ab16);
    cudaGetSymbolAddress((void**)&As,   g_As16);

    const int nx4 = N_CTX * D_MODEL / 4;
    const int nw4 = D_MODEL * D_MODEL / 4;

    // Pre-passes
    split_f16_kernel<<<(nx4 + 255) / 256, 256>>>(x, xb, xs, nx4);
    split_f16_kernel<<<(nw4 + 255) / 256, 256>>>(Wqk, wqkb, wqks, nw4);
    round_f16_kernel<<<(nw4 + 255) / 256, 256>>>(Wov, wov, nw4);
    transpose_f16_kernel<<<dim3(D_MODEL / 32, N_CTX / 32), dim3(32, 8)>>>(x, xT, N_CTX, D_MODEL);

    // 1) Q = x @ Wqk^T  (3-pass; epilogue writes split Qb/Qs)
    hgemm<0, 0, 3, 1><<<dim3(D_MODEL / 128, N_CTX / 128), 256>>>(
        xb, xs, wqkb, wqks, nullptr, Qb, Qs, N_CTX, D_MODEL, D_MODEL);

    // 2) S = Q @ x^T  (causal blocks only, 3-pass, fp32 store)
    hgemm<1, 0, 3, 0><<<dim3(N_CTX / 128, N_CTX / 128), 256>>>(
        Qb, Qs, xb, xs, S, nullptr, nullptr, N_CTX, N_CTX, D_MODEL);

    // 3) P = causal_softmax(S) -> split fp16 Pb/Ps
    softmax_kernel<<<N_CTX, 256>>>(S, Pb, Ps, N_CTX);

    // 4) A = P @ (x^T)^T  (2-pass: P split, x single; causal k-limit; split store)
    hgemm<0, 1, 2, 1><<<dim3(D_MODEL / 128, N_CTX / 128), 256>>>(
        Pb, Ps, xT, nullptr, nullptr, Ab, As, N_CTX, D_MODEL, N_CTX);

    // 5) out = A @ Wov^T  (2-pass: A split, Wov single; fp32 store)
    hgemm<0, 0, 2, 0><<<dim3(D_MODEL / 128, N_CTX / 128), 256>>>(
        Ab, As, wov, nullptr, out, nullptr, nullptr, N_CTX, D_MODEL, D_MODEL);
}

// round 8
// speedup vs baseline: 1.9515x; 1.1110x over previous
#include <cuda_runtime.h>
#include <cuda_fp16.h>
#include <math.h>
#include <stdint.h>

#define N_CTX   4096
#define D_MODEL 2048

// ---------------------------------------------------------------------------
// Scratch (__device__ globals; allocation-free rule)
// ---------------------------------------------------------------------------
__device__ __half g_xb16 [(size_t)N_CTX * D_MODEL];
__device__ __half g_xs16 [(size_t)N_CTX * D_MODEL];
__device__ __half g_xT16 [(size_t)D_MODEL * N_CTX];   // x^T, single fp16
__device__ __half g_wqkb16[(size_t)D_MODEL * D_MODEL];
__device__ __half g_wqks16[(size_t)D_MODEL * D_MODEL];
__device__ __half g_wov16 [(size_t)D_MODEL * D_MODEL];
__device__ __half g_Qb16 [(size_t)N_CTX * D_MODEL];
__device__ __half g_Qs16 [(size_t)N_CTX * D_MODEL];
__device__ float  g_S    [(size_t)N_CTX * N_CTX];
__device__ __half g_Pb16 [(size_t)N_CTX * N_CTX];
__device__ __half g_Ps16 [(size_t)N_CTX * N_CTX];
__device__ __half g_Ab16 [(size_t)N_CTX * D_MODEL];
__device__ __half g_As16 [(size_t)N_CTX * D_MODEL];

// ---------------------------------------------------------------------------
// helpers
// ---------------------------------------------------------------------------
__device__ __forceinline__ void mma_f16(float c[4],
                                        uint32_t a0, uint32_t a1, uint32_t a2, uint32_t a3,
                                        uint32_t b0, uint32_t b1) {
    asm volatile(
        "mma.sync.aligned.m16n8k16.row.col.f32.f16.f16.f32 "
        "{%0,%1,%2,%3}, {%4,%5,%6,%7}, {%8,%9}, {%0,%1,%2,%3};"
        : "+f"(c[0]), "+f"(c[1]), "+f"(c[2]), "+f"(c[3])
        : "r"(a0), "r"(a1), "r"(a2), "r"(a3), "r"(b0), "r"(b1));
}

__device__ __forceinline__ void ldm_x4(uint32_t r[4], uint32_t saddr) {
    asm volatile("ldmatrix.sync.aligned.m8n8.x4.shared.b16 {%0,%1,%2,%3}, [%4];"
                 : "=r"(r[0]), "=r"(r[1]), "=r"(r[2]), "=r"(r[3]) : "r"(saddr));
}

__device__ __forceinline__ void cp_async16(void* smem, const void* gmem) {
    uint32_t s = (uint32_t)__cvta_generic_to_shared(smem);
    asm volatile("cp.async.cg.shared.global [%0], [%1], 16;" :: "r"(s), "l"(gmem));
}

// ---------------------------------------------------------------------------
// Elementwise pre-passes
// ---------------------------------------------------------------------------
__global__ __launch_bounds__(256)
void split_f16_kernel(const float* __restrict__ src,
                      __half* __restrict__ big, __half* __restrict__ sml, int n4)
{
    int i = blockIdx.x * 256 + threadIdx.x;
    if (i >= n4) return;
    float4 v = ((const float4*)src)[i];
    __half b0 = __float2half_rn(v.x), b1 = __float2half_rn(v.y);
    __half b2 = __float2half_rn(v.z), b3 = __float2half_rn(v.w);
    __half s0 = __float2half_rn(v.x - __half2float(b0));
    __half s1 = __float2half_rn(v.y - __half2float(b1));
    __half s2 = __float2half_rn(v.z - __half2float(b2));
    __half s3 = __float2half_rn(v.w - __half2float(b3));
    ((__half2*)big)[i * 2 + 0] = __halves2half2(b0, b1);
    ((__half2*)big)[i * 2 + 1] = __halves2half2(b2, b3);
    ((__half2*)sml)[i * 2 + 0] = __halves2half2(s0, s1);
    ((__half2*)sml)[i * 2 + 1] = __halves2half2(s2, s3);
}

__global__ __launch_bounds__(256)
void round_f16_kernel(const float* __restrict__ src, __half* __restrict__ dst, int n4)
{
    int i = blockIdx.x * 256 + threadIdx.x;
    if (i >= n4) return;
    float4 v = ((const float4*)src)[i];
    ((__half2*)dst)[i * 2 + 0] = __halves2half2(__float2half_rn(v.x), __float2half_rn(v.y));
    ((__half2*)dst)[i * 2 + 1] = __halves2half2(__float2half_rn(v.z), __float2half_rn(v.w));
}

// dst[Ccols, R] = fp16(src[R, Ccols]^T)
__global__ __launch_bounds__(256)
void transpose_f16_kernel(const float* __restrict__ src, __half* __restrict__ dst,
                          int R, int Ccols)
{
    __shared__ float t[32][33];
    int bx = blockIdx.x * 32, by = blockIdx.y * 32;
    int x = bx + threadIdx.x;
    for (int i = threadIdx.y; i < 32; i += 8)
        t[i][threadIdx.x] = src[(size_t)(by + i) * Ccols + x];
    __syncthreads();
    int ox = by + threadIdx.x;
    for (int i = threadIdx.y; i < 32; i += 8)
        dst[(size_t)(bx + i) * R + ox] = __float2half_rn(t[threadIdx.x][i]);
}

// ---------------------------------------------------------------------------
// fp16 split GEMM: C[M,N] = A[M,K] @ B^T, A:[M,K], B:[N,K], both K-major fp16.
//   PASSES=3: (As*Bb + Ab*Bs + Ab*Bb); PASSES=2: (As*Bb + Ab*Bb)
//   CSKIP: skip blocks above diagonal; CK: k-range limited to m0+128
//   EPI: 0 = fp32 store to C; 1 = split fp16 store to Cb/Cs
// 256 threads, 8 warps (2x4), warp tile 64x32, block 128x128x32, m16n8k16,
// ldmatrix.x4 fragment loads (PK=40 padding -> conflict-free).
// ---------------------------------------------------------------------------
template <int CSKIP, int CK, int PASSES, int EPI>
__global__ __launch_bounds__(256)
void hgemm(const __half* __restrict__ Ab_, const __half* __restrict__ As_,
           const __half* __restrict__ Bb_, const __half* __restrict__ Bs_,
           float* __restrict__ C, __half* __restrict__ Cb, __half* __restrict__ Cs,
           int M, int N, int K)
{
    constexpr int BM = 128, BN = 128, BK = 32, PK = 40;  // PK: padded halves/row
    constexpr int BNs = (PASSES == 3) ? BN : 1;

    __shared__ __half sAb[2][BM][PK];
    __shared__ __half sAs[2][BM][PK];
    __shared__ __half sBb[2][BN][PK];
    __shared__ __half sBs[2][BNs][PK];

    const int m0 = blockIdx.y * BM;
    const int n0 = blockIdx.x * BN;
    if (CSKIP && n0 >= m0 + BM) return;

    const int kEnd = CK ? min(K, m0 + BM) : K;
    const int nK   = kEnd / BK;

    const int tid  = threadIdx.x;
    const int warp = tid >> 5;
    const int lane = tid & 31;
    const int wm0  = (warp & 1) * 64;
    const int wn0  = (warp >> 1) * 32;
    const int g    = lane >> 2;
    const int tg   = lane & 3;

    // ldmatrix per-lane source row/col (halves) within a 4-matrix group
    const int lm  = lane >> 3;          // matrix id 0..3
    const int lr  = lane & 7;           // row within matrix
    const int aRow = (lm & 1) * 8 + lr; // A: m0/m1 = row halves, m2/m3 = k-high
    const int aCol = (lm >> 1) * 8;
    const int bRow = (lm >> 1) * 8 + lr;// B: m0/m1 = k halves of nt even, m2/m3 = nt odd
    const int bCol = (lm & 1) * 8;

    const uint32_t uAb = (uint32_t)__cvta_generic_to_shared(&sAb[0][0][0]);
    const uint32_t uAs = (uint32_t)__cvta_generic_to_shared(&sAs[0][0][0]);
    const uint32_t uBb = (uint32_t)__cvta_generic_to_shared(&sBb[0][0][0]);
    const uint32_t uBs = (uint32_t)__cvta_generic_to_shared(&sBs[0][0][0]);
    constexpr uint32_t BUFA = (uint32_t)BM * PK * 2;   // bytes per buffer
    constexpr uint32_t BUFB = (uint32_t)BN * PK * 2;

    float acc[4][4][4];
    #pragma unroll
    for (int i = 0; i < 4; i++)
        #pragma unroll
        for (int j = 0; j < 4; j++)
            #pragma unroll
            for (int r = 0; r < 4; r++) acc[i][j][r] = 0.0f;

    auto loadStage = [&](int buf, int k0) {
        #pragma unroll
        for (int i = 0; i < 2; i++) {
            int idx = tid + i * 256;          // 0..511
            int row = idx >> 2;               // 0..127
            int c8  = (idx & 3) * 8;          // halves offset: 0,8,16,24
            cp_async16(&sAb[buf][row][c8], Ab_ + (size_t)(m0 + row) * K + k0 + c8);
            cp_async16(&sAs[buf][row][c8], As_ + (size_t)(m0 + row) * K + k0 + c8);
            cp_async16(&sBb[buf][row][c8], Bb_ + (size_t)(n0 + row) * K + k0 + c8);
            if constexpr (PASSES == 3)
                cp_async16(&sBs[buf][row][c8], Bs_ + (size_t)(n0 + row) * K + k0 + c8);
        }
    };

    auto compute = [&](int buf) {
        #pragma unroll
        for (int ks = 0; ks < 2; ks++) {
            const int kb = ks * 16;
            uint32_t Ab[4][4], As[4][4];
            uint32_t Bb[4][2], Bs[4][2];

            const uint32_t aoff = (uint32_t)((wm0 + aRow) * PK + kb + aCol) * 2;
            const uint32_t boff = (uint32_t)((wn0 + bRow) * PK + kb + bCol) * 2;

            #pragma unroll
            for (int mt = 0; mt < 4; mt++) {
                ldm_x4(Ab[mt], uAb + buf * BUFA + aoff + (uint32_t)(mt * 16 * PK * 2));
                ldm_x4(As[mt], uAs + buf * BUFA + aoff + (uint32_t)(mt * 16 * PK * 2));
            }
            #pragma unroll
            for (int j = 0; j < 2; j++) {
                uint32_t t[4];
                ldm_x4(t, uBb + buf * BUFB + boff + (uint32_t)(j * 16 * PK * 2));
                Bb[2 * j][0] = t[0]; Bb[2 * j][1] = t[1];
                Bb[2 * j + 1][0] = t[2]; Bb[2 * j + 1][1] = t[3];
                if constexpr (PASSES == 3) {
                    ldm_x4(t, uBs + buf * BUFB + boff + (uint32_t)(j * 16 * PK * 2));
                    Bs[2 * j][0] = t[0]; Bs[2 * j][1] = t[1];
                    Bs[2 * j + 1][0] = t[2]; Bs[2 * j + 1][1] = t[3];
                }
            }

            // Pass-ordered: consecutive MMAs hit different accumulators.
            #pragma unroll
            for (int mt = 0; mt < 4; mt++)
                #pragma unroll
                for (int nt = 0; nt < 4; nt++)
                    mma_f16(acc[mt][nt], As[mt][0], As[mt][1], As[mt][2], As[mt][3],
                            Bb[nt][0], Bb[nt][1]);
            if constexpr (PASSES == 3) {
                #pragma unroll
                for (int mt = 0; mt < 4; mt++)
                    #pragma unroll
                    for (int nt = 0; nt < 4; nt++)
                        mma_f16(acc[mt][nt], Ab[mt][0], Ab[mt][1], Ab[mt][2], Ab[mt][3],
                                Bs[nt][0], Bs[nt][1]);
            }
            #pragma unroll
            for (int mt = 0; mt < 4; mt++)
                #pragma unroll
                for (int nt = 0; nt < 4; nt++)
                    mma_f16(acc[mt][nt], Ab[mt][0], Ab[mt][1], Ab[mt][2], Ab[mt][3],
                            Bb[nt][0], Bb[nt][1]);
        }
    };

    loadStage(0, 0);
    asm volatile("cp.async.commit_group;" ::: "memory");

    for (int kt = 0; kt < nK; kt++) {
        if (kt + 1 < nK) {
            loadStage((kt + 1) & 1, (kt + 1) * BK);
            asm volatile("cp.async.commit_group;" ::: "memory");
            asm volatile("cp.async.wait_group 1;" ::: "memory");
        } else {
            asm volatile("cp.async.wait_group 0;" ::: "memory");
        }
        __syncthreads();
        compute(kt & 1);
        __syncthreads();
    }

    // ---- epilogue ----
    #pragma unroll
    for (int mt = 0; mt < 4; mt++) {
        #pragma unroll
        for (int nt = 0; nt < 4; nt++) {
            int r = m0 + wm0 + mt * 16 + g;
            int c = n0 + wn0 + nt * 8 + 2 * tg;
            #pragma unroll
            for (int h = 0; h < 2; h++) {
                float v0 = acc[mt][nt][h * 2 + 0];
                float v1 = acc[mt][nt][h * 2 + 1];
                size_t off = (size_t)(r + h * 8) * N + c;
                if constexpr (EPI == 0) {
                    *(float2*)(C + off) = make_float2(v0, v1);
                } else {
                    __half b0 = __float2half_rn(v0), b1 = __float2half_rn(v1);
                    *(__half2*)(Cb + off) = __halves2half2(b0, b1);
                    *(__half2*)(Cs + off) = __halves2half2(
                        __float2half_rn(v0 - __half2float(b0)),
                        __float2half_rn(v1 - __half2float(b1)));
                }
            }
        }
    }
}

// ---------------------------------------------------------------------------
// Causal row softmax: reads fp32 scores, writes split-fp16 P (zero tail).
// ---------------------------------------------------------------------------
__global__ __launch_bounds__(256)
void softmax_kernel(float* __restrict__ S,
                    __half* __restrict__ Pb, __half* __restrict__ Ps, int n)
{
    const int row   = blockIdx.x;
    float* srow     = S + (size_t)row * n;
    const int valid = row + 1;
    const int tid   = threadIdx.x;

    __shared__ float red[256];

    float m = -INFINITY;
    for (int j = tid; j < valid; j += 256) m = fmaxf(m, srow[j]);
    red[tid] = m;
    __syncthreads();
    #pragma unroll
    for (int s = 128; s > 0; s >>= 1) {
        if (tid < s) red[tid] = fmaxf(red[tid], red[tid + s]);
        __syncthreads();
    }
    m = red[0];
    __syncthreads();

    float sum = 0.0f;
    for (int j = tid; j < valid; j += 256) {
        float e = __expf(srow[j] - m);
        srow[j] = e;
        sum += e;
    }
    red[tid] = sum;
    __syncthreads();
    #pragma unroll
    for (int s = 128; s > 0; s >>= 1) {
        if (tid < s) red[tid] += red[tid + s];
        __syncthreads();
    }
    const float inv = 1.0f / red[0];

    for (int j = tid; j < n; j += 256) {
        float p = (j < valid) ? srow[j] * inv : 0.0f;
        __half b = __float2half_rn(p);
        Pb[(size_t)row * n + j] = b;
        Ps[(size_t)row * n + j] = __float2half_rn(p - __half2float(b));
    }
}

// ---------------------------------------------------------------------------
extern "C" void kernel_launch(void* const* d_in, const int* in_sizes, int n_in,
                              void* d_out, int out_size)
{
    const float* x   = (const float*)d_in[0];
    const float* Wqk = (const float*)d_in[1];
    const float* Wov = (const float*)d_in[2];
    float* out       = (float*)d_out;

    __half *xb, *xs, *xT, *wqkb, *wqks, *wov, *Qb, *Qs, *Pb, *Ps, *Ab, *As;
    float *S;
    cudaGetSymbolAddress((void**)&xb,   g_xb16);
    cudaGetSymbolAddress((void**)&xs,   g_xs16);
    cudaGetSymbolAddress((void**)&xT,   g_xT16);
    cudaGetSymbolAddress((void**)&wqkb, g_wqkb16);
    cudaGetSymbolAddress((void**)&wqks, g_wqks16);
    cudaGetSymbolAddress((void**)&wov,  g_wov16);
    cudaGetSymbolAddress((void**)&Qb,   g_Qb16);
    cudaGetSymbolAddress((void**)&Qs,   g_Qs16);
    cudaGetSymbolAddress((void**)&S,    g_S);
    cudaGetSymbolAddress((void**)&Pb,   g_Pb16);
    cudaGetSymbolAddress((void**)&Ps,   g_Ps16);
    cudaGetSymbolAddress((void**)&Ab,   g_Ab16);
    cudaGetSymbolAddress((void**)&As,   g_As16);

    const int nx4 = N_CTX * D_MODEL / 4;
    const int nw4 = D_MODEL * D_MODEL / 4;

    // Pre-passes
    split_f16_kernel<<<(nx4 + 255) / 256, 256>>>(x, xb, xs, nx4);
    split_f16_kernel<<<(nw4 + 255) / 256, 256>>>(Wqk, wqkb, wqks, nw4);
    round_f16_kernel<<<(nw4 + 255) / 256, 256>>>(Wov, wov, nw4);
    transpose_f16_kernel<<<dim3(D_MODEL / 32, N_CTX / 32), dim3(32, 8)>>>(x, xT, N_CTX, D_MODEL);

    // 1) Q = x @ Wqk^T  (3-pass; epilogue writes split Qb/Qs)
    hgemm<0, 0, 3, 1><<<dim3(D_MODEL / 128, N_CTX / 128), 256>>>(
        xb, xs, wqkb, wqks, nullptr, Qb, Qs, N_CTX, D_MODEL, D_MODEL);

    // 2) S = Q @ x^T  (causal blocks only, 3-pass, fp32 store)
    hgemm<1, 0, 3, 0><<<dim3(N_CTX / 128, N_CTX / 128), 256>>>(
        Qb, Qs, xb, xs, S, nullptr, nullptr, N_CTX, N_CTX, D_MODEL);

    // 3) P = causal_softmax(S) -> split fp16 Pb/Ps
    softmax_kernel<<<N_CTX, 256>>>(S, Pb, Ps, N_CTX);

    // 4) A = P @ (x^T)^T  (2-pass: P split, x single; causal k-limit; split store)
    hgemm<0, 1, 2, 1><<<dim3(D_MODEL / 128, N_CTX / 128), 256>>>(
        Pb, Ps, xT, nullptr, nullptr, Ab, As, N_CTX, D_MODEL, N_CTX);

    // 5) out = A @ Wov^T  (2-pass: A split, Wov single; fp32 store)
    hgemm<0, 0, 2, 0><<<dim3(D_MODEL / 128, N_CTX / 128), 256>>>(
        Ab, As, wov, nullptr, out, nullptr, nullptr, N_CTX, D_MODEL, D_MODEL);
}

// round 11
// speedup vs baseline: 2.1935x; 1.1240x over previous
#include <cuda_runtime.h>
#include <cuda_fp16.h>
#include <math.h>
#include <stdint.h>

#define N_CTX   4096
#define D_MODEL 2048

// ---------------------------------------------------------------------------
// Scratch (__device__ globals; allocation-free rule)
// ---------------------------------------------------------------------------
__device__ __half g_xb16 [(size_t)N_CTX * D_MODEL];
__device__ __half g_xs16 [(size_t)N_CTX * D_MODEL];
__device__ __half g_xT16 [(size_t)D_MODEL * N_CTX];   // x^T, single fp16
__device__ __half g_wqkb16[(size_t)D_MODEL * D_MODEL];
__device__ __half g_wqks16[(size_t)D_MODEL * D_MODEL];
__device__ __half g_wov16 [(size_t)D_MODEL * D_MODEL];
__device__ __half g_Qb16 [(size_t)N_CTX * D_MODEL];
__device__ __half g_Qs16 [(size_t)N_CTX * D_MODEL];
__device__ float  g_S    [(size_t)N_CTX * N_CTX];
__device__ __half g_P16  [(size_t)N_CTX * N_CTX];
__device__ __half g_A16  [(size_t)N_CTX * D_MODEL];

// ---------------------------------------------------------------------------
// helpers
// ---------------------------------------------------------------------------
__device__ __forceinline__ void mma_f16(float c[4],
                                        uint32_t a0, uint32_t a1, uint32_t a2, uint32_t a3,
                                        uint32_t b0, uint32_t b1) {
    asm volatile(
        "mma.sync.aligned.m16n8k16.row.col.f32.f16.f16.f32 "
        "{%0,%1,%2,%3}, {%4,%5,%6,%7}, {%8,%9}, {%0,%1,%2,%3};"
        : "+f"(c[0]), "+f"(c[1]), "+f"(c[2]), "+f"(c[3])
        : "r"(a0), "r"(a1), "r"(a2), "r"(a3), "r"(b0), "r"(b1));
}

__device__ __forceinline__ void ldm_x4(uint32_t r[4], uint32_t saddr) {
    asm volatile("ldmatrix.sync.aligned.m8n8.x4.shared.b16 {%0,%1,%2,%3}, [%4];"
                 : "=r"(r[0]), "=r"(r[1]), "=r"(r[2]), "=r"(r[3]) : "r"(saddr));
}

__device__ __forceinline__ void cp_async16(void* smem, const void* gmem) {
    uint32_t s = (uint32_t)__cvta_generic_to_shared(smem);
    asm volatile("cp.async.cg.shared.global [%0], [%1], 16;" :: "r"(s), "l"(gmem));
}

// ---------------------------------------------------------------------------
// Elementwise pre-passes
// ---------------------------------------------------------------------------
__global__ __launch_bounds__(256)
void split_f16_kernel(const float* __restrict__ src,
                      __half* __restrict__ big, __half* __restrict__ sml, int n4)
{
    int i = blockIdx.x * 256 + threadIdx.x;
    if (i >= n4) return;
    float4 v = ((const float4*)src)[i];
    __half b0 = __float2half_rn(v.x), b1 = __float2half_rn(v.y);
    __half b2 = __float2half_rn(v.z), b3 = __float2half_rn(v.w);
    __half s0 = __float2half_rn(v.x - __half2float(b0));
    __half s1 = __float2half_rn(v.y - __half2float(b1));
    __half s2 = __float2half_rn(v.z - __half2float(b2));
    __half s3 = __float2half_rn(v.w - __half2float(b3));
    ((__half2*)big)[i * 2 + 0] = __halves2half2(b0, b1);
    ((__half2*)big)[i * 2 + 1] = __halves2half2(b2, b3);
    ((__half2*)sml)[i * 2 + 0] = __halves2half2(s0, s1);
    ((__half2*)sml)[i * 2 + 1] = __halves2half2(s2, s3);
}

__global__ __launch_bounds__(256)
void round_f16_kernel(const float* __restrict__ src, __half* __restrict__ dst, int n4)
{
    int i = blockIdx.x * 256 + threadIdx.x;
    if (i >= n4) return;
    float4 v = ((const float4*)src)[i];
    ((__half2*)dst)[i * 2 + 0] = __halves2half2(__float2half_rn(v.x), __float2half_rn(v.y));
    ((__half2*)dst)[i * 2 + 1] = __halves2half2(__float2half_rn(v.z), __float2half_rn(v.w));
}

// dst[Ccols, R] = fp16(src[R, Ccols]^T)
__global__ __launch_bounds__(256)
void transpose_f16_kernel(const float* __restrict__ src, __half* __restrict__ dst,
                          int R, int Ccols)
{
    __shared__ float t[32][33];
    int bx = blockIdx.x * 32, by = blockIdx.y * 32;
    int x = bx + threadIdx.x;
    for (int i = threadIdx.y; i < 32; i += 8)
        t[i][threadIdx.x] = src[(size_t)(by + i) * Ccols + x];
    __syncthreads();
    int ox = by + threadIdx.x;
    for (int i = threadIdx.y; i < 32; i += 8)
        dst[(size_t)(bx + i) * R + ox] = __float2half_rn(t[threadIdx.x][i]);
}

// ---------------------------------------------------------------------------
// fp16 split GEMM: C[M,N] = A[M,K] @ B^T, A:[M,K], B:[N,K], both K-major fp16.
//   PASSES=3: As*Bb + Ab*Bs + Ab*Bb;  PASSES=1: Ab*Bb only
//   CSKIP: skip blocks above diagonal; CK: k-range limited to m0+128
//   EPI: 0 = fp32 store to C; 1 = split fp16 store Cb/Cs; 2 = single fp16 Cb
// 256 threads, 8 warps (2x4), warp tile 64x32, block 128x128x32, m16n8k16,
// ldmatrix.x4 fragment loads (PK=40 padding -> conflict-free).
// ---------------------------------------------------------------------------
template <int CSKIP, int CK, int PASSES, int EPI, int OCC>
__global__ __launch_bounds__(256, OCC)
void hgemm(const __half* __restrict__ Ab_, const __half* __restrict__ As_,
           const __half* __restrict__ Bb_, const __half* __restrict__ Bs_,
           float* __restrict__ C, __half* __restrict__ Cb, __half* __restrict__ Cs,
           int M, int N, int K)
{
    constexpr int BM = 128, BN = 128, BK = 32, PK = 40;  // PK: padded halves/row
    constexpr int BMs = (PASSES >= 2) ? BM : 1;
    constexpr int BNs = (PASSES == 3) ? BN : 1;

    __shared__ __half sAb[2][BM][PK];
    __shared__ __half sAs[2][BMs][PK];
    __shared__ __half sBb[2][BN][PK];
    __shared__ __half sBs[2][BNs][PK];

    const int m0 = blockIdx.y * BM;
    const int n0 = blockIdx.x * BN;
    if (CSKIP && n0 >= m0 + BM) return;

    const int kEnd = CK ? min(K, m0 + BM) : K;
    const int nK   = kEnd / BK;

    const int tid  = threadIdx.x;
    const int warp = tid >> 5;
    const int lane = tid & 31;
    const int wm0  = (warp & 1) * 64;
    const int wn0  = (warp >> 1) * 32;
    const int g    = lane >> 2;
    const int tg   = lane & 3;

    // ldmatrix per-lane source row/col (halves) within a 4-matrix group
    const int lm  = lane >> 3;
    const int lr  = lane & 7;
    const int aRow = (lm & 1) * 8 + lr;
    const int aCol = (lm >> 1) * 8;
    const int bRow = (lm >> 1) * 8 + lr;
    const int bCol = (lm & 1) * 8;

    const uint32_t uAb = (uint32_t)__cvta_generic_to_shared(&sAb[0][0][0]);
    const uint32_t uAs = (uint32_t)__cvta_generic_to_shared(&sAs[0][0][0]);
    const uint32_t uBb = (uint32_t)__cvta_generic_to_shared(&sBb[0][0][0]);
    const uint32_t uBs = (uint32_t)__cvta_generic_to_shared(&sBs[0][0][0]);
    constexpr uint32_t BUFA = (uint32_t)BM * PK * 2;
    constexpr uint32_t BUFB = (uint32_t)BN * PK * 2;

    float acc[4][4][4];
    #pragma unroll
    for (int i = 0; i < 4; i++)
        #pragma unroll
        for (int j = 0; j < 4; j++)
            #pragma unroll
            for (int r = 0; r < 4; r++) acc[i][j][r] = 0.0f;

    auto loadStage = [&](int buf, int k0) {
        #pragma unroll
        for (int i = 0; i < 2; i++) {
            int idx = tid + i * 256;
            int row = idx >> 2;
            int c8  = (idx & 3) * 8;
            cp_async16(&sAb[buf][row][c8], Ab_ + (size_t)(m0 + row) * K + k0 + c8);
            cp_async16(&sBb[buf][row][c8], Bb_ + (size_t)(n0 + row) * K + k0 + c8);
            if constexpr (PASSES >= 2)
                cp_async16(&sAs[buf][row][c8], As_ + (size_t)(m0 + row) * K + k0 + c8);
            if constexpr (PASSES == 3)
                cp_async16(&sBs[buf][row][c8], Bs_ + (size_t)(n0 + row) * K + k0 + c8);
        }
    };

    auto compute = [&](int buf) {
        #pragma unroll
        for (int ks = 0; ks < 2; ks++) {
            const int kb = ks * 16;
            uint32_t Ab[4][4], As[4][4];
            uint32_t Bb[4][2], Bs[4][2];

            const uint32_t aoff = (uint32_t)((wm0 + aRow) * PK + kb + aCol) * 2;
            const uint32_t boff = (uint32_t)((wn0 + bRow) * PK + kb + bCol) * 2;

            #pragma unroll
            for (int mt = 0; mt < 4; mt++) {
                ldm_x4(Ab[mt], uAb + buf * BUFA + aoff + (uint32_t)(mt * 16 * PK * 2));
                if constexpr (PASSES >= 2)
                    ldm_x4(As[mt], uAs + buf * BUFA + aoff + (uint32_t)(mt * 16 * PK * 2));
            }
            #pragma unroll
            for (int j = 0; j < 2; j++) {
                uint32_t t[4];
                ldm_x4(t, uBb + buf * BUFB + boff + (uint32_t)(j * 16 * PK * 2));
                Bb[2 * j][0] = t[0]; Bb[2 * j][1] = t[1];
                Bb[2 * j + 1][0] = t[2]; Bb[2 * j + 1][1] = t[3];
                if constexpr (PASSES == 3) {
                    ldm_x4(t, uBs + buf * BUFB + boff + (uint32_t)(j * 16 * PK * 2));
                    Bs[2 * j][0] = t[0]; Bs[2 * j][1] = t[1];
                    Bs[2 * j + 1][0] = t[2]; Bs[2 * j + 1][1] = t[3];
                }
            }

            if constexpr (PASSES >= 2) {
                #pragma unroll
                for (int mt = 0; mt < 4; mt++)
                    #pragma unroll
                    for (int nt = 0; nt < 4; nt++)
                        mma_f16(acc[mt][nt], As[mt][0], As[mt][1], As[mt][2], As[mt][3],
                                Bb[nt][0], Bb[nt][1]);
            }
            if constexpr (PASSES == 3) {
                #pragma unroll
                for (int mt = 0; mt < 4; mt++)
                    #pragma unroll
                    for (int nt = 0; nt < 4; nt++)
                        mma_f16(acc[mt][nt], Ab[mt][0], Ab[mt][1], Ab[mt][2], Ab[mt][3],
                                Bs[nt][0], Bs[nt][1]);
            }
            #pragma unroll
            for (int mt = 0; mt < 4; mt++)
                #pragma unroll
                for (int nt = 0; nt < 4; nt++)
                    mma_f16(acc[mt][nt], Ab[mt][0], Ab[mt][1], Ab[mt][2], Ab[mt][3],
                            Bb[nt][0], Bb[nt][1]);
        }
    };

    loadStage(0, 0);
    asm volatile("cp.async.commit_group;" ::: "memory");

    for (int kt = 0; kt < nK; kt++) {
        if (kt + 1 < nK) {
            loadStage((kt + 1) & 1, (kt + 1) * BK);
            asm volatile("cp.async.commit_group;" ::: "memory");
            asm volatile("cp.async.wait_group 1;" ::: "memory");
        } else {
            asm volatile("cp.async.wait_group 0;" ::: "memory");
        }
        __syncthreads();
        compute(kt & 1);
        __syncthreads();
    }

    // ---- epilogue ----
    #pragma unroll
    for (int mt = 0; mt < 4; mt++) {
        #pragma unroll
        for (int nt = 0; nt < 4; nt++) {
            int r = m0 + wm0 + mt * 16 + g;
            int c = n0 + wn0 + nt * 8 + 2 * tg;
            #pragma unroll
            for (int h = 0; h < 2; h++) {
                float v0 = acc[mt][nt][h * 2 + 0];
                float v1 = acc[mt][nt][h * 2 + 1];
                size_t off = (size_t)(r + h * 8) * N + c;
                if constexpr (EPI == 0) {
                    *(float2*)(C + off) = make_float2(v0, v1);
                } else if constexpr (EPI == 1) {
                    __half b0 = __float2half_rn(v0), b1 = __float2half_rn(v1);
                    *(__half2*)(Cb + off) = __halves2half2(b0, b1);
                    *(__half2*)(Cs + off) = __halves2half2(
                        __float2half_rn(v0 - __half2float(b0)),
                        __float2half_rn(v1 - __half2float(b1)));
                } else {
                    *(__half2*)(Cb + off) = __halves2half2(__float2half_rn(v0),
                                                           __float2half_rn(v1));
                }
            }
        }
    }
}

// ---------------------------------------------------------------------------
// Causal row softmax: reads fp32 scores, writes single fp16 P (zero tail).
// ---------------------------------------------------------------------------
__global__ __launch_bounds__(256)
void softmax_kernel(float* __restrict__ S, __half* __restrict__ P, int n)
{
    const int row   = blockIdx.x;
    float* srow     = S + (size_t)row * n;
    const int valid = row + 1;
    const int tid   = threadIdx.x;

    __shared__ float red[256];

    float m = -INFINITY;
    for (int j = tid; j < valid; j += 256) m = fmaxf(m, srow[j]);
    red[tid] = m;
    __syncthreads();
    #pragma unroll
    for (int s = 128; s > 0; s >>= 1) {
        if (tid < s) red[tid] = fmaxf(red[tid], red[tid + s]);
        __syncthreads();
    }
    m = red[0];
    __syncthreads();

    float sum = 0.0f;
    for (int j = tid; j < valid; j += 256) {
        float e = __expf(srow[j] - m);
        srow[j] = e;
        sum += e;
    }
    red[tid] = sum;
    __syncthreads();
    #pragma unroll
    for (int s = 128; s > 0; s >>= 1) {
        if (tid < s) red[tid] += red[tid + s];
        __syncthreads();
    }
    const float inv = 1.0f / red[0];

    for (int j = tid; j < n; j += 256) {
        float p = (j < valid) ? srow[j] * inv : 0.0f;
        P[(size_t)row * n + j] = __float2half_rn(p);
    }
}

// ---------------------------------------------------------------------------
extern "C" void kernel_launch(void* const* d_in, const int* in_sizes, int n_in,
                              void* d_out, int out_size)
{
    const float* x   = (const float*)d_in[0];
    const float* Wqk = (const float*)d_in[1];
    const float* Wov = (const float*)d_in[2];
    float* out       = (float*)d_out;

    __half *xb, *xs, *xT, *wqkb, *wqks, *wov, *Qb, *Qs, *P, *A;
    float *S;
    cudaGetSymbolAddress((void**)&xb,   g_xb16);
    cudaGetSymbolAddress((void**)&xs,   g_xs16);
    cudaGetSymbolAddress((void**)&xT,   g_xT16);
    cudaGetSymbolAddress((void**)&wqkb, g_wqkb16);
    cudaGetSymbolAddress((void**)&wqks, g_wqks16);
    cudaGetSymbolAddress((void**)&wov,  g_wov16);
    cudaGetSymbolAddress((void**)&Qb,   g_Qb16);
    cudaGetSymbolAddress((void**)&Qs,   g_Qs16);
    cudaGetSymbolAddress((void**)&S,    g_S);
    cudaGetSymbolAddress((void**)&P,    g_P16);
    cudaGetSymbolAddress((void**)&A,    g_A16);

    const int nx4 = N_CTX * D_MODEL / 4;
    const int nw4 = D_MODEL * D_MODEL / 4;

    // Pre-passes
    split_f16_kernel<<<(nx4 + 255) / 256, 256>>>(x, xb, xs, nx4);
    split_f16_kernel<<<(nw4 + 255) / 256, 256>>>(Wqk, wqkb, wqks, nw4);
    round_f16_kernel<<<(nw4 + 255) / 256, 256>>>(Wov, wov, nw4);
    transpose_f16_kernel<<<dim3(D_MODEL / 32, N_CTX / 32), dim3(32, 8)>>>(x, xT, N_CTX, D_MODEL);

    // 1) Q = x @ Wqk^T  (3-pass; epilogue writes split Qb/Qs)
    hgemm<0, 0, 3, 1, 1><<<dim3(D_MODEL / 128, N_CTX / 128), 256>>>(
        xb, xs, wqkb, wqks, nullptr, Qb, Qs, N_CTX, D_MODEL, D_MODEL);

    // 2) S = Q @ x^T  (causal blocks only, 3-pass, fp32 store)
    hgemm<1, 0, 3, 0, 1><<<dim3(N_CTX / 128, N_CTX / 128), 256>>>(
        Qb, Qs, xb, xs, S, nullptr, nullptr, N_CTX, N_CTX, D_MODEL);

    // 3) P = causal_softmax(S) -> single fp16
    softmax_kernel<<<N_CTX, 256>>>(S, P, N_CTX);

    // 4) A = P @ (x^T)^T  (1-pass; causal k-limit; fp16 store)
    hgemm<0, 1, 1, 2, 2><<<dim3(D_MODEL / 128, N_CTX / 128), 256>>>(
        P, nullptr, xT, nullptr, nullptr, A, nullptr, N_CTX, D_MODEL, N_CTX);

    // 5) out = A @ Wov^T  (1-pass; fp32 store)
    hgemm<0, 0, 1, 0, 2><<<dim3(D_MODEL / 128, N_CTX / 128), 256>>>(
        A, nullptr, wov, nullptr, out, nullptr, nullptr, N_CTX, D_MODEL, D_MODEL);
}

// round 14
// speedup vs baseline: 2.5862x; 1.1790x over previous
#include <cuda_runtime.h>
#include <cuda_fp16.h>
#include <math.h>
#include <stdint.h>

#define N_CTX   4096
#define D_MODEL 2048

// ---------------------------------------------------------------------------
// Scratch (__device__ globals; allocation-free rule)
// ---------------------------------------------------------------------------
__device__ __half g_xb16 [(size_t)N_CTX * D_MODEL];
__device__ __half g_xs16 [(size_t)N_CTX * D_MODEL];
__device__ __half g_xT16 [(size_t)D_MODEL * N_CTX];   // x^T, single fp16
__device__ __half g_wqkb16[(size_t)D_MODEL * D_MODEL];
__device__ __half g_wqks16[(size_t)D_MODEL * D_MODEL];
__device__ __half g_wov16 [(size_t)D_MODEL * D_MODEL];
__device__ __half g_Qb16 [(size_t)N_CTX * D_MODEL];
__device__ __half g_Qs16 [(size_t)N_CTX * D_MODEL];
__device__ float  g_S    [(size_t)N_CTX * N_CTX];
__device__ __half g_P16  [(size_t)N_CTX * N_CTX];
__device__ __half g_A16  [(size_t)N_CTX * D_MODEL];

// ---------------------------------------------------------------------------
// helpers
// ---------------------------------------------------------------------------
__device__ __forceinline__ void mma_f16(float c[4],
                                        uint32_t a0, uint32_t a1, uint32_t a2, uint32_t a3,
                                        uint32_t b0, uint32_t b1) {
    asm volatile(
        "mma.sync.aligned.m16n8k16.row.col.f32.f16.f16.f32 "
        "{%0,%1,%2,%3}, {%4,%5,%6,%7}, {%8,%9}, {%0,%1,%2,%3};"
        : "+f"(c[0]), "+f"(c[1]), "+f"(c[2]), "+f"(c[3])
        : "r"(a0), "r"(a1), "r"(a2), "r"(a3), "r"(b0), "r"(b1));
}

__device__ __forceinline__ void ldm_x4(uint32_t r[4], uint32_t saddr) {
    asm volatile("ldmatrix.sync.aligned.m8n8.x4.shared.b16 {%0,%1,%2,%3}, [%4];"
                 : "=r"(r[0]), "=r"(r[1]), "=r"(r[2]), "=r"(r[3]) : "r"(saddr));
}

__device__ __forceinline__ void cp_async16(void* smem, const void* gmem) {
    uint32_t s = (uint32_t)__cvta_generic_to_shared(smem);
    asm volatile("cp.async.cg.shared.global [%0], [%1], 16;" :: "r"(s), "l"(gmem));
}
__device__ __forceinline__ void cp_commit() {
    asm volatile("cp.async.commit_group;" ::: "memory");
}
template <int Nn>
__device__ __forceinline__ void cp_wait() {
    asm volatile("cp.async.wait_group %0;" :: "n"(Nn) : "memory");
}

// ---------------------------------------------------------------------------
// Elementwise pre-passes
// ---------------------------------------------------------------------------
// Fused: xb/xs (split fp16, row-major) + xT (single fp16, transposed).
__global__ __launch_bounds__(256)
void prep_x_kernel(const float* __restrict__ x,
                   __half* __restrict__ xb, __half* __restrict__ xs,
                   __half* __restrict__ xT, int R, int Cc)
{
    __shared__ float t[32][33];
    const int bx = blockIdx.x * 32, by = blockIdx.y * 32;
    const int tx = threadIdx.x, ty = threadIdx.y;
    const int col = bx + tx;
    for (int i = ty; i < 32; i += 8) {
        float v = x[(size_t)(by + i) * Cc + col];
        t[i][tx] = v;
        __half b = __float2half_rn(v);
        size_t off = (size_t)(by + i) * Cc + col;
        xb[off] = b;
        xs[off] = __float2half_rn(v - __half2float(b));
    }
    __syncthreads();
    const int orow = by + tx;
    for (int i = ty; i < 32; i += 8)
        xT[(size_t)(bx + i) * R + orow] = __float2half_rn(t[tx][i]);
}

__global__ __launch_bounds__(256)
void split_f16_kernel(const float* __restrict__ src,
                      __half* __restrict__ big, __half* __restrict__ sml, int n4)
{
    int i = blockIdx.x * 256 + threadIdx.x;
    if (i >= n4) return;
    float4 v = ((const float4*)src)[i];
    __half b0 = __float2half_rn(v.x), b1 = __float2half_rn(v.y);
    __half b2 = __float2half_rn(v.z), b3 = __float2half_rn(v.w);
    ((__half2*)big)[i * 2 + 0] = __halves2half2(b0, b1);
    ((__half2*)big)[i * 2 + 1] = __halves2half2(b2, b3);
    ((__half2*)sml)[i * 2 + 0] = __halves2half2(
        __float2half_rn(v.x - __half2float(b0)), __float2half_rn(v.y - __half2float(b1)));
    ((__half2*)sml)[i * 2 + 1] = __halves2half2(
        __float2half_rn(v.z - __half2float(b2)), __float2half_rn(v.w - __half2float(b3)));
}

__global__ __launch_bounds__(256)
void round_f16_kernel(const float* __restrict__ src, __half* __restrict__ dst, int n4)
{
    int i = blockIdx.x * 256 + threadIdx.x;
    if (i >= n4) return;
    float4 v = ((const float4*)src)[i];
    ((__half2*)dst)[i * 2 + 0] = __halves2half2(__float2half_rn(v.x), __float2half_rn(v.y));
    ((__half2*)dst)[i * 2 + 1] = __halves2half2(__float2half_rn(v.z), __float2half_rn(v.w));
}

// ---------------------------------------------------------------------------
// fp16 split GEMM: C[M,N] = A[M,K] @ B^T, A:[M,K], B:[N,K], both K-major fp16.
//   PASSES=3: As*Bb + Ab*Bs + Ab*Bb;  PASSES=1: Ab*Bb only
//   CSKIP: skip blocks above diagonal; CK: k-range limited to m0+128
//   EPI: 0 = fp32 store to C; 1 = split fp16 store Cb/Cs; 2 = single fp16 Cb
// 256 threads, 8 warps (2x4), warp tile 64x32, block 128x128x32, m16n8k16,
// ldmatrix.x4 loads (PK=40 conflict-free), 3-stage cp.async pipeline with a
// SINGLE __syncthreads per k-tile (dynamic smem).
// ---------------------------------------------------------------------------
template <int CSKIP, int CK, int PASSES, int EPI, int OCC>
__global__ __launch_bounds__(256, OCC)
void hgemm(const __half* __restrict__ Ab_, const __half* __restrict__ As_,
           const __half* __restrict__ Bb_, const __half* __restrict__ Bs_,
           float* __restrict__ C, __half* __restrict__ Cb, __half* __restrict__ Cs,
           int M, int N, int K)
{
    constexpr int BM = 128, BN = 128, BK = 32, PK = 40;
    constexpr int NS = 3;                        // pipeline stages
    constexpr int TILE_H = BM * PK;              // halves per tile array (5120)
    constexpr int ARR = (PASSES == 3) ? 4 : ((PASSES == 2) ? 3 : 2);
    // stage layout (halves): [Ab | Bb | As | Bs]

    extern __shared__ __half dsm[];

    const int m0 = blockIdx.y * BM;
    const int n0 = blockIdx.x * BN;
    if (CSKIP && n0 >= m0 + BM) return;

    const int kEnd = CK ? min(K, m0 + BM) : K;
    const int nK   = kEnd / BK;

    const int tid  = threadIdx.x;
    const int warp = tid >> 5;
    const int lane = tid & 31;
    const int wm0  = (warp & 1) * 64;
    const int wn0  = (warp >> 1) * 32;
    const int g    = lane >> 2;
    const int tg   = lane & 3;

    // ldmatrix per-lane source row/col (halves)
    const int lm  = lane >> 3;
    const int lr  = lane & 7;
    const int aRow = (lm & 1) * 8 + lr;
    const int aCol = (lm >> 1) * 8;
    const int bRow = (lm >> 1) * 8 + lr;
    const int bCol = (lm & 1) * 8;

    const uint32_t u0 = (uint32_t)__cvta_generic_to_shared(dsm);
    constexpr uint32_t STAGE_B = (uint32_t)ARR * TILE_H * 2;   // bytes per stage
    constexpr uint32_t OFF_B   = (uint32_t)TILE_H * 2;         // Bb offset
    constexpr uint32_t OFF_AS  = (uint32_t)2 * TILE_H * 2;     // As offset
    constexpr uint32_t OFF_BS  = (uint32_t)3 * TILE_H * 2;     // Bs offset

    float acc[4][4][4];
    #pragma unroll
    for (int i = 0; i < 4; i++)
        #pragma unroll
        for (int j = 0; j < 4; j++)
            #pragma unroll
            for (int r = 0; r < 4; r++) acc[i][j][r] = 0.0f;

    auto loadStage = [&](int s, int k0) {
        __half* st = dsm + (size_t)s * ARR * TILE_H;
        #pragma unroll
        for (int i = 0; i < 2; i++) {
            int idx = tid + i * 256;
            int row = idx >> 2;
            int c8  = (idx & 3) * 8;
            cp_async16(st + row * PK + c8,              Ab_ + (size_t)(m0 + row) * K + k0 + c8);
            cp_async16(st + TILE_H + row * PK + c8,     Bb_ + (size_t)(n0 + row) * K + k0 + c8);
            if constexpr (PASSES >= 2)
                cp_async16(st + 2 * TILE_H + row * PK + c8, As_ + (size_t)(m0 + row) * K + k0 + c8);
            if constexpr (PASSES == 3)
                cp_async16(st + 3 * TILE_H + row * PK + c8, Bs_ + (size_t)(n0 + row) * K + k0 + c8);
        }
    };

    auto compute = [&](int s) {
        const uint32_t ub = u0 + (uint32_t)s * STAGE_B;
        #pragma unroll
        for (int ks = 0; ks < 2; ks++) {
            const int kb = ks * 16;
            uint32_t Ab[4][4], As[4][4];
            uint32_t Bb[4][2], Bs[4][2];

            const uint32_t aoff = (uint32_t)((wm0 + aRow) * PK + kb + aCol) * 2;
            const uint32_t boff = (uint32_t)((wn0 + bRow) * PK + kb + bCol) * 2;

            #pragma unroll
            for (int mt = 0; mt < 4; mt++) {
                ldm_x4(Ab[mt], ub + aoff + (uint32_t)(mt * 16 * PK * 2));
                if constexpr (PASSES >= 2)
                    ldm_x4(As[mt], ub + OFF_AS + aoff + (uint32_t)(mt * 16 * PK * 2));
            }
            #pragma unroll
            for (int j = 0; j < 2; j++) {
                uint32_t t[4];
                ldm_x4(t, ub + OFF_B + boff + (uint32_t)(j * 16 * PK * 2));
                Bb[2 * j][0] = t[0]; Bb[2 * j][1] = t[1];
                Bb[2 * j + 1][0] = t[2]; Bb[2 * j + 1][1] = t[3];
                if constexpr (PASSES == 3) {
                    ldm_x4(t, ub + OFF_BS + boff + (uint32_t)(j * 16 * PK * 2));
                    Bs[2 * j][0] = t[0]; Bs[2 * j][1] = t[1];
                    Bs[2 * j + 1][0] = t[2]; Bs[2 * j + 1][1] = t[3];
                }
            }

            if constexpr (PASSES >= 2) {
                #pragma unroll
                for (int mt = 0; mt < 4; mt++)
                    #pragma unroll
                    for (int nt = 0; nt < 4; nt++)
                        mma_f16(acc[mt][nt], As[mt][0], As[mt][1], As[mt][2], As[mt][3],
                                Bb[nt][0], Bb[nt][1]);
            }
            if constexpr (PASSES == 3) {
                #pragma unroll
                for (int mt = 0; mt < 4; mt++)
                    #pragma unroll
                    for (int nt = 0; nt < 4; nt++)
                        mma_f16(acc[mt][nt], Ab[mt][0], Ab[mt][1], Ab[mt][2], Ab[mt][3],
                                Bs[nt][0], Bs[nt][1]);
            }
            #pragma unroll
            for (int mt = 0; mt < 4; mt++)
                #pragma unroll
                for (int nt = 0; nt < 4; nt++)
                    mma_f16(acc[mt][nt], Ab[mt][0], Ab[mt][1], Ab[mt][2], Ab[mt][3],
                            Bb[nt][0], Bb[nt][1]);
        }
    };

    // Prologue: 2 stages in flight (nK >= 4 always here)
    loadStage(0, 0);        cp_commit();
    loadStage(1, BK);       cp_commit();

    // Mainloop: one __syncthreads per k-tile.
    // At iter kt: groups 0..kt+1 committed; wait<1> => groups <= kt done.
    // load(kt+2) writes buf (kt+2)%3 == (kt-1)%3, last read before this
    // iteration's barrier -> hazard-free.
    for (int kt = 0; kt < nK; kt++) {
        cp_wait<1>();
        __syncthreads();
        compute(kt % NS);
        if (kt + 2 < nK) loadStage((kt + 2) % NS, (kt + 2) * BK);
        cp_commit();
    }

    // ---- epilogue ----
    #pragma unroll
    for (int mt = 0; mt < 4; mt++) {
        #pragma unroll
        for (int nt = 0; nt < 4; nt++) {
            int r = m0 + wm0 + mt * 16 + g;
            int c = n0 + wn0 + nt * 8 + 2 * tg;
            #pragma unroll
            for (int h = 0; h < 2; h++) {
                float v0 = acc[mt][nt][h * 2 + 0];
                float v1 = acc[mt][nt][h * 2 + 1];
                size_t off = (size_t)(r + h * 8) * N + c;
                if constexpr (EPI == 0) {
                    *(float2*)(C + off) = make_float2(v0, v1);
                } else if constexpr (EPI == 1) {
                    __half b0 = __float2half_rn(v0), b1 = __float2half_rn(v1);
                    *(__half2*)(Cb + off) = __halves2half2(b0, b1);
                    *(__half2*)(Cs + off) = __halves2half2(
                        __float2half_rn(v0 - __half2float(b0)),
                        __float2half_rn(v1 - __half2float(b1)));
                } else {
                    *(__half2*)(Cb + off) = __halves2half2(__float2half_rn(v0),
                                                           __float2half_rn(v1));
                }
            }
        }
    }
}

// ---------------------------------------------------------------------------
// Causal row softmax: reads fp32 scores, writes single fp16 P (zero tail).
// ---------------------------------------------------------------------------
__global__ __launch_bounds__(256)
void softmax_kernel(float* __restrict__ S, __half* __restrict__ P, int n)
{
    const int row   = blockIdx.x;
    float* srow     = S + (size_t)row * n;
    const int valid = row + 1;
    const int tid   = threadIdx.x;

    __shared__ float red[256];

    float m = -INFINITY;
    for (int j = tid; j < valid; j += 256) m = fmaxf(m, srow[j]);
    red[tid] = m;
    __syncthreads();
    #pragma unroll
    for (int s = 128; s > 0; s >>= 1) {
        if (tid < s) red[tid] = fmaxf(red[tid], red[tid + s]);
        __syncthreads();
    }
    m = red[0];
    __syncthreads();

    float sum = 0.0f;
    for (int j = tid; j < valid; j += 256) {
        float e = __expf(srow[j] - m);
        srow[j] = e;
        sum += e;
    }
    red[tid] = sum;
    __syncthreads();
    #pragma unroll
    for (int s = 128; s > 0; s >>= 1) {
        if (tid < s) red[tid] += red[tid + s];
        __syncthreads();
    }
    const float inv = 1.0f / red[0];

    for (int j = tid; j < n; j += 256) {
        float p = (j < valid) ? srow[j] * inv : 0.0f;
        P[(size_t)row * n + j] = __float2half_rn(p);
    }
}

// ---------------------------------------------------------------------------
extern "C" void kernel_launch(void* const* d_in, const int* in_sizes, int n_in,
                              void* d_out, int out_size)
{
    const float* x   = (const float*)d_in[0];
    const float* Wqk = (const float*)d_in[1];
    const float* Wov = (const float*)d_in[2];
    float* out       = (float*)d_out;

    __half *xb, *xs, *xT, *wqkb, *wqks, *wov, *Qb, *Qs, *P, *A;
    float *S;
    cudaGetSymbolAddress((void**)&xb,   g_xb16);
    cudaGetSymbolAddress((void**)&xs,   g_xs16);
    cudaGetSymbolAddress((void**)&xT,   g_xT16);
    cudaGetSymbolAddress((void**)&wqkb, g_wqkb16);
    cudaGetSymbolAddress((void**)&wqks, g_wqks16);
    cudaGetSymbolAddress((void**)&wov,  g_wov16);
    cudaGetSymbolAddress((void**)&Qb,   g_Qb16);
    cudaGetSymbolAddress((void**)&Qs,   g_Qs16);
    cudaGetSymbolAddress((void**)&S,    g_S);
    cudaGetSymbolAddress((void**)&P,    g_P16);
    cudaGetSymbolAddress((void**)&A,    g_A16);

    const int nw4 = D_MODEL * D_MODEL / 4;

    // Dynamic smem sizes: 3 stages x ARR arrays x 5120 halves x 2B
    const int SM3 = 3 * 4 * 128 * 40 * 2;   // 3-pass: 122880
    const int SM1 = 3 * 2 * 128 * 40 * 2;   // 1-pass: 61440

    static bool attr_done = false;
    if (!attr_done) {
        cudaFuncSetAttribute(hgemm<0, 0, 3, 1, 1>, cudaFuncAttributeMaxDynamicSharedMemorySize, SM3);
        cudaFuncSetAttribute(hgemm<1, 0, 3, 0, 1>, cudaFuncAttributeMaxDynamicSharedMemorySize, SM3);
        cudaFuncSetAttribute(hgemm<0, 1, 1, 2, 2>, cudaFuncAttributeMaxDynamicSharedMemorySize, SM1);
        cudaFuncSetAttribute(hgemm<0, 0, 1, 0, 2>, cudaFuncAttributeMaxDynamicSharedMemorySize, SM1);
        attr_done = true;
    }

    // Pre-passes
    prep_x_kernel<<<dim3(D_MODEL / 32, N_CTX / 32), dim3(32, 8)>>>(x, xb, xs, xT, N_CTX, D_MODEL);
    split_f16_kernel<<<(nw4 + 255) / 256, 256>>>(Wqk, wqkb, wqks, nw4);
    round_f16_kernel<<<(nw4 + 255) / 256, 256>>>(Wov, wov, nw4);

    // 1) Q = x @ Wqk^T  (3-pass; epilogue writes split Qb/Qs)
    hgemm<0, 0, 3, 1, 1><<<dim3(D_MODEL / 128, N_CTX / 128), 256, SM3>>>(
        xb, xs, wqkb, wqks, nullptr, Qb, Qs, N_CTX, D_MODEL, D_MODEL);

    // 2) S = Q @ x^T  (causal blocks only, 3-pass, fp32 store)
    hgemm<1, 0, 3, 0, 1><<<dim3(N_CTX / 128, N_CTX / 128), 256, SM3>>>(
        Qb, Qs, xb, xs, S, nullptr, nullptr, N_CTX, N_CTX, D_MODEL);

    // 3) P = causal_softmax(S) -> single fp16
    softmax_kernel<<<N_CTX, 256>>>(S, P, N_CTX);

    // 4) A = P @ (x^T)^T  (1-pass; causal k-limit; fp16 store)
    hgemm<0, 1, 1, 2, 2><<<dim3(D_MODEL / 128, N_CTX / 128), 256, SM1>>>(
        P, nullptr, xT, nullptr, nullptr, A, nullptr, N_CTX, D_MODEL, N_CTX);

    // 5) out = A @ Wov^T  (1-pass; fp32 store)
    hgemm<0, 0, 1, 0, 2><<<dim3(D_MODEL / 128, N_CTX / 128), 256, SM1>>>(
        A, nullptr, wov, nullptr, out, nullptr, nullptr, N_CTX, D_MODEL, D_MODEL);
}